// round 1
// baseline (speedup 1.0000x reference)
#include <cuda_runtime.h>

// ---------------- problem constants ----------------
#define UN  100000
#define INC 50000
#define NN  150000
#define DD  64
#define KK  128
#define EE  1250000
#define LL  2

// ---------------- device scratch (static; no allocations) ----------------
__device__ float g_ek[NN * DD];      // current layer embedding
__device__ float g_accum[NN * DD];   // running final sum
__device__ int   g_cnt[NN];
__device__ int   g_rowptr[NN + 1];
__device__ int   g_wp[NN];
__device__ int   g_ecol[EE];         // CSR: tail indices
__device__ float g_eval[EE];         // CSR: adj values
__device__ float g_ag[EE];           // per-edge alpha (graph), CSR order
__device__ float g_ai[EE];           // per-edge alpha (intent), CSR order
__device__ float g_inormg[NN];
__device__ float g_inormi[NN];
__device__ float g_dinvg[NN];
__device__ float g_dinvi[NN];

// ---------------- CSR build ----------------
__global__ void zero_cnt_kernel() {
    int i = blockIdx.x * blockDim.x + threadIdx.x;
    if (i < NN) g_cnt[i] = 0;
}

__global__ void hist_kernel(const int* __restrict__ h) {
    int e = blockIdx.x * blockDim.x + threadIdx.x;
    if (e < EE) atomicAdd(&g_cnt[h[e]], 1);
}

__global__ void scan_kernel() {
    __shared__ int s[1024];
    int tid = threadIdx.x;
    const int CH = (NN + 1023) / 1024;
    int base = tid * CH;
    int sum = 0;
    for (int i = 0; i < CH; i++) {
        int idx = base + i;
        if (idx < NN) sum += g_cnt[idx];
    }
    s[tid] = sum;
    __syncthreads();
    for (int off = 1; off < 1024; off <<= 1) {
        int v = (tid >= off) ? s[tid - off] : 0;
        __syncthreads();
        s[tid] += v;
        __syncthreads();
    }
    int run = (tid == 0) ? 0 : s[tid - 1];
    for (int i = 0; i < CH; i++) {
        int idx = base + i;
        if (idx < NN) {
            g_rowptr[idx] = run;
            g_wp[idx]     = run;
            run += g_cnt[idx];
        }
    }
    if (tid == 0) g_rowptr[NN] = EE;
}

__global__ void scatter_kernel(const int* __restrict__ h, const int* __restrict__ t,
                               const float* __restrict__ adj) {
    int e = blockIdx.x * blockDim.x + threadIdx.x;
    if (e >= EE) return;
    int hn = h[e];
    int p  = atomicAdd(&g_wp[hn], 1);
    g_ecol[p] = t[e];
    g_eval[p] = adj[e];
}

// ---------------- init ----------------
__global__ void init_ek_kernel(const float4* __restrict__ ue, const float4* __restrict__ ie) {
    int i = blockIdx.x * blockDim.x + threadIdx.x;      // float4 index
    const int TOT = NN * DD / 4, UD4 = UN * DD / 4;
    if (i >= TOT) return;
    float4 v = (i < UD4) ? ue[i] : ie[i - UD4];
    ((float4*)g_ek)[i]    = v;
    ((float4*)g_accum)[i] = v;
}

// ---------------- SpMM: gnn = A @ ek (warp per node) ----------------
__global__ void spmm_gnn_kernel(float* __restrict__ out) {
    int gw   = (blockIdx.x * blockDim.x + threadIdx.x) >> 5;
    int lane = threadIdx.x & 31;
    if (gw >= NN) return;
    int s = g_rowptr[gw], e = g_rowptr[gw + 1];
    float2 acc = make_float2(0.f, 0.f);
    for (int p = s; p < e; p++) {
        int   tt = g_ecol[p];
        float v  = g_eval[p];
        float2 x = *(const float2*)(g_ek + (size_t)tt * DD + lane * 2);
        acc.x = fmaf(v, x.x, acc.x);
        acc.y = fmaf(v, x.y, acc.y);
    }
    *(float2*)(out + (size_t)gw * DD + lane * 2) = acc;
}

// ---------------- fused intent: softmax(ek@W)@W^T per 128-row tile ----------------
#define TM   128
#define ASP  132
#define BTP  68
#define PSP  132
#define IT_SMEM_FLOATS (64 * ASP + 64 * KK + KK * BTP + TM * PSP)
#define IT_SMEM_BYTES  (IT_SMEM_FLOATS * 4)

__global__ void __launch_bounds__(256, 1)
intent_kernel(const float* __restrict__ W, float* __restrict__ outIntl,
              int nodeBase, int nodeCount) {
    extern __shared__ float sm[];
    float* As = sm;                  // [64][ASP]  A^T tile
    float* Bs = As + 64 * ASP;       // [64][128]  W
    float* Bt = Bs + 64 * KK;        // [128][BTP] W^T
    float* Ps = Bt + KK * BTP;       // [128][PSP] logits -> probs

    int tid = threadIdx.x;
    int tx = tid & 15, ty = tid >> 4;
    int rowTile = blockIdx.x * TM;

    // load W into Bs (row-major copy) and Bt (transposed)
#pragma unroll
    for (int it = 0; it < 8; it++) {
        int i = tid + it * 256;                  // 0..2047 float4s
        float4 v = ((const float4*)W)[i];
        int d = i >> 5;
        int k = (i << 2) & 127;
        *(float4*)(Bs + d * KK + k) = v;
        Bt[(k + 0) * BTP + d] = v.x;
        Bt[(k + 1) * BTP + d] = v.y;
        Bt[(k + 2) * BTP + d] = v.z;
        Bt[(k + 3) * BTP + d] = v.w;
    }
    // load A tile transposed (zero-pad OOB rows)
#pragma unroll
    for (int it = 0; it < 8; it++) {
        int i  = tid + it * 256;                 // 0..2047 float4s
        int rr = i >> 4;
        int d0 = (i << 2) & 63;
        float4 v = make_float4(0.f, 0.f, 0.f, 0.f);
        int r = rowTile + rr;
        if (r < nodeCount) v = *(const float4*)(g_ek + (size_t)(nodeBase + r) * DD + d0);
        As[(d0 + 0) * ASP + rr] = v.x;
        As[(d0 + 1) * ASP + rr] = v.y;
        As[(d0 + 2) * ASP + rr] = v.z;
        As[(d0 + 3) * ASP + rr] = v.w;
    }
    __syncthreads();

    // GEMM1: logits[128][128]
    float acc[8][8];
#pragma unroll
    for (int i = 0; i < 8; i++)
#pragma unroll
        for (int j = 0; j < 8; j++) acc[i][j] = 0.f;

    const int r0 = ty * 8, k0 = tx * 8;
#pragma unroll 8
    for (int d = 0; d < DD; d++) {
        float a[8], b[8];
        *(float4*)(a)     = *(const float4*)(As + d * ASP + r0);
        *(float4*)(a + 4) = *(const float4*)(As + d * ASP + r0 + 4);
        *(float4*)(b)     = *(const float4*)(Bs + d * KK + k0);
        *(float4*)(b + 4) = *(const float4*)(Bs + d * KK + k0 + 4);
#pragma unroll
        for (int i = 0; i < 8; i++)
#pragma unroll
            for (int j = 0; j < 8; j++) acc[i][j] = fmaf(a[i], b[j], acc[i][j]);
    }
#pragma unroll
    for (int i = 0; i < 8; i++) {
        *(float4*)(Ps + (r0 + i) * PSP + k0)     = make_float4(acc[i][0], acc[i][1], acc[i][2], acc[i][3]);
        *(float4*)(Ps + (r0 + i) * PSP + k0 + 4) = make_float4(acc[i][4], acc[i][5], acc[i][6], acc[i][7]);
    }
    __syncthreads();

    // row softmax (warp per row, 16 rows per warp)
    int warp = tid >> 5, lane = tid & 31;
    for (int rr = warp; rr < TM; rr += 8) {
        float4 v = *(float4*)(Ps + rr * PSP + lane * 4);
        float m = fmaxf(fmaxf(v.x, v.y), fmaxf(v.z, v.w));
#pragma unroll
        for (int o = 16; o > 0; o >>= 1) m = fmaxf(m, __shfl_xor_sync(0xffffffffu, m, o));
        float e0 = __expf(v.x - m), e1 = __expf(v.y - m);
        float e2 = __expf(v.z - m), e3 = __expf(v.w - m);
        float s = e0 + e1 + e2 + e3;
#pragma unroll
        for (int o = 16; o > 0; o >>= 1) s += __shfl_xor_sync(0xffffffffu, s, o);
        float inv = 1.0f / s;
        *(float4*)(Ps + rr * PSP + lane * 4) = make_float4(e0 * inv, e1 * inv, e2 * inv, e3 * inv);
    }
    __syncthreads();

    // GEMM2: out[128][64] = P @ W^T
    float4 acc2[8];
#pragma unroll
    for (int i = 0; i < 8; i++) acc2[i] = make_float4(0.f, 0.f, 0.f, 0.f);
    const int d0o = tx * 4;
#pragma unroll 2
    for (int k = 0; k < KK; k += 4) {
        float4 p[8];
#pragma unroll
        for (int i = 0; i < 8; i++) p[i] = *(const float4*)(Ps + (r0 + i) * PSP + k);
        float4 b0 = *(const float4*)(Bt + (k + 0) * BTP + d0o);
        float4 b1 = *(const float4*)(Bt + (k + 1) * BTP + d0o);
        float4 b2 = *(const float4*)(Bt + (k + 2) * BTP + d0o);
        float4 b3 = *(const float4*)(Bt + (k + 3) * BTP + d0o);
#pragma unroll
        for (int i = 0; i < 8; i++) {
            acc2[i].x = fmaf(p[i].x, b0.x, fmaf(p[i].y, b1.x, fmaf(p[i].z, b2.x, fmaf(p[i].w, b3.x, acc2[i].x))));
            acc2[i].y = fmaf(p[i].x, b0.y, fmaf(p[i].y, b1.y, fmaf(p[i].z, b2.y, fmaf(p[i].w, b3.y, acc2[i].y))));
            acc2[i].z = fmaf(p[i].x, b0.z, fmaf(p[i].y, b1.z, fmaf(p[i].z, b2.z, fmaf(p[i].w, b3.z, acc2[i].z))));
            acc2[i].w = fmaf(p[i].x, b0.w, fmaf(p[i].y, b1.w, fmaf(p[i].z, b2.w, fmaf(p[i].w, b3.w, acc2[i].w))));
        }
    }
#pragma unroll
    for (int i = 0; i < 8; i++) {
        int r = rowTile + r0 + i;
        if (r < nodeCount)
            *(float4*)(outIntl + (size_t)(nodeBase + r) * DD + d0o) = acc2[i];
    }
}

// ---------------- node inverse norms of gnn & intl ----------------
__global__ void norms_kernel(const float* __restrict__ gnn, const float* __restrict__ itl) {
    int gw   = (blockIdx.x * blockDim.x + threadIdx.x) >> 5;
    int lane = threadIdx.x & 31;
    if (gw >= NN) return;
    float2 a = *(const float2*)(gnn + (size_t)gw * DD + lane * 2);
    float2 b = *(const float2*)(itl + (size_t)gw * DD + lane * 2);
    float sg = a.x * a.x + a.y * a.y;
    float si = b.x * b.x + b.y * b.y;
#pragma unroll
    for (int o = 16; o > 0; o >>= 1) {
        sg += __shfl_xor_sync(0xffffffffu, sg, o);
        si += __shfl_xor_sync(0xffffffffu, si, o);
    }
    if (lane == 0) {
        g_inormg[gw] = 1.f / fmaxf(sqrtf(sg), 1e-12f);
        g_inormi[gw] = 1.f / fmaxf(sqrtf(si), 1e-12f);
    }
}

// ---------------- per-edge alpha + row sums (warp per node, no atomics) ----------------
__global__ void alpha_kernel(const float* __restrict__ gnn, const float* __restrict__ itl) {
    int gw   = (blockIdx.x * blockDim.x + threadIdx.x) >> 5;
    int lane = threadIdx.x & 31;
    if (gw >= NN) return;
    int s = g_rowptr[gw], e = g_rowptr[gw + 1];
    float2 hg = *(const float2*)(gnn + (size_t)gw * DD + lane * 2);
    float2 hi = *(const float2*)(itl + (size_t)gw * DD + lane * 2);
    float ihg = g_inormg[gw], ihi = g_inormi[gw];
    float rsg = 0.f, rsi = 0.f;
    for (int p = s; p < e; p++) {
        int tt = g_ecol[p];
        float2 tg = *(const float2*)(gnn + (size_t)tt * DD + lane * 2);
        float2 ti = *(const float2*)(itl + (size_t)tt * DD + lane * 2);
        float dg = hg.x * tg.x + hg.y * tg.y;
        float di = hi.x * ti.x + hi.y * ti.y;
#pragma unroll
        for (int o = 16; o > 0; o >>= 1) {
            dg += __shfl_xor_sync(0xffffffffu, dg, o);
            di += __shfl_xor_sync(0xffffffffu, di, o);
        }
        float ag = fmaf(dg * ihg, g_inormg[tt], 1.f) * 0.5f;
        float ai = fmaf(di * ihi, g_inormi[tt], 1.f) * 0.5f;
        if (lane == 0) { g_ag[p] = ag; g_ai[p] = ai; }
        rsg += ag;
        rsi += ai;
    }
    if (lane == 0) {
        g_dinvg[gw] = rsg > 0.f ? 1.f / rsg : 0.f;
        g_dinvi[gw] = rsi > 0.f ? 1.f / rsi : 0.f;
    }
}

// ---------------- second SpMM: gaa & iaa in one pass ----------------
__global__ void spmm2_kernel(float* __restrict__ gaa, float* __restrict__ iaa) {
    int gw   = (blockIdx.x * blockDim.x + threadIdx.x) >> 5;
    int lane = threadIdx.x & 31;
    if (gw >= NN) return;
    int s = g_rowptr[gw], e = g_rowptr[gw + 1];
    float dg = g_dinvg[gw], di = g_dinvi[gw];
    float2 ag = make_float2(0.f, 0.f), ai = make_float2(0.f, 0.f);
    for (int p = s; p < e; p++) {
        int   tt = g_ecol[p];
        float wg = g_ag[p] * dg;
        float wi = g_ai[p] * di;
        float2 x = *(const float2*)(g_ek + (size_t)tt * DD + lane * 2);
        ag.x = fmaf(wg, x.x, ag.x); ag.y = fmaf(wg, x.y, ag.y);
        ai.x = fmaf(wi, x.x, ai.x); ai.y = fmaf(wi, x.y, ai.y);
    }
    *(float2*)(gaa + (size_t)gw * DD + lane * 2) = ag;
    *(float2*)(iaa + (size_t)gw * DD + lane * 2) = ai;
}

// ---------------- combine: e_{l+1}, accum, optional final store ----------------
__global__ void combine_kernel(const float4* __restrict__ gnn, const float4* __restrict__ itl,
                               const float4* __restrict__ gaa, const float4* __restrict__ iaa,
                               float4* __restrict__ finalOut) {
    int i = blockIdx.x * blockDim.x + threadIdx.x;
    const int TOT = NN * DD / 4;
    if (i >= TOT) return;
    float4 g = gnn[i], n = itl[i], a = gaa[i], b = iaa[i];
    float4 ev = ((const float4*)g_ek)[i];
    float4 en;
    en.x = g.x + n.x + a.x + b.x + ev.x;
    en.y = g.y + n.y + a.y + b.y + ev.y;
    en.z = g.z + n.z + a.z + b.z + ev.z;
    en.w = g.w + n.w + a.w + b.w + ev.w;
    float4 ac = ((const float4*)g_accum)[i];
    ac.x += en.x; ac.y += en.y; ac.z += en.z; ac.w += en.w;
    ((float4*)g_accum)[i] = ac;
    ((float4*)g_ek)[i]    = en;
    if (finalOut) finalOut[i] = ac;
}

// ---------------- launch ----------------
extern "C" void kernel_launch(void* const* d_in, const int* in_sizes, int n_in,
                              void* d_out, int out_size) {
    const float* user_emb = (const float*)d_in[0];
    const float* item_emb = (const float*)d_in[1];
    const float* Wu       = (const float*)d_in[2];
    const float* Wi       = (const float*)d_in[3];
    const float* adj      = (const float*)d_in[4];
    const int*   h        = (const int*)d_in[5];
    const int*   t        = (const int*)d_in[6];
    (void)in_sizes; (void)n_in; (void)out_size;

    float* out = (float*)d_out;
    const size_t ND = (size_t)NN * DD;
    float* out_ua  = out;                    // [N*D] = ua | ia
    float* out_gnn = out + ND;               // [L][N][D]
    float* out_int = out_gnn + (size_t)LL * ND;
    float* out_gaa = out_int + (size_t)LL * ND;
    float* out_iaa = out_gaa + (size_t)LL * ND;

    cudaFuncSetAttribute(intent_kernel, cudaFuncAttributeMaxDynamicSharedMemorySize, IT_SMEM_BYTES);

    const int TPB = 256;
    zero_cnt_kernel<<<(NN + TPB - 1) / TPB, TPB>>>();
    hist_kernel<<<(EE + TPB - 1) / TPB, TPB>>>(h);
    scan_kernel<<<1, 1024>>>();
    scatter_kernel<<<(EE + TPB - 1) / TPB, TPB>>>(h, t, adj);
    init_ek_kernel<<<(NN * DD / 4 + TPB - 1) / TPB, TPB>>>((const float4*)user_emb,
                                                           (const float4*)item_emb);

    const int NODE_BLOCKS = (NN * 32 + TPB - 1) / TPB;   // warp per node
    for (int l = 0; l < LL; l++) {
        float* gnn = out_gnn + (size_t)l * ND;
        float* itl = out_int + (size_t)l * ND;
        float* gaa = out_gaa + (size_t)l * ND;
        float* iaa = out_iaa + (size_t)l * ND;

        spmm_gnn_kernel<<<NODE_BLOCKS, TPB>>>(gnn);
        intent_kernel<<<(UN + TM - 1) / TM, 256, IT_SMEM_BYTES>>>(Wu, itl, 0, UN);
        intent_kernel<<<(INC + TM - 1) / TM, 256, IT_SMEM_BYTES>>>(Wi, itl, UN, INC);
        norms_kernel<<<NODE_BLOCKS, TPB>>>(gnn, itl);
        alpha_kernel<<<NODE_BLOCKS, TPB>>>(gnn, itl);
        spmm2_kernel<<<NODE_BLOCKS, TPB>>>(gaa, iaa);
        combine_kernel<<<(NN * DD / 4 + TPB - 1) / TPB, TPB>>>(
            (const float4*)gnn, (const float4*)itl, (const float4*)gaa, (const float4*)iaa,
            (l == LL - 1) ? (float4*)out_ua : (float4*)nullptr);
    }
}

// round 2
// speedup vs baseline: 1.3124x; 1.3124x over previous
#include <cuda_runtime.h>

// ---------------- problem constants ----------------
#define UN  100000
#define INC 50000
#define NN  150000
#define DD  64
#define KK  128
#define EE  1250000
#define LL  2

typedef unsigned long long u64;

// ---------------- device scratch (static; no allocations) ----------------
__device__ float g_ekA[NN * DD];
__device__ float g_ekB[NN * DD];
__device__ float g_accum[NN * DD];
__device__ int   g_cnt[NN];
__device__ int   g_rowptr[NN + 1];
__device__ int   g_wp[NN];
__device__ int   g_ecol[EE];
__device__ float g_eval[EE];
__device__ float g_inormg[NN];
__device__ float g_inormi[NN];
__device__ int   g_bsum[160];
__device__ int   g_boff[160];

// ---------------- f32x2 packed-math helpers ----------------
__device__ __forceinline__ u64 pk2(float x, float y) {
    u64 r; asm("mov.b64 %0, {%1, %2};" : "=l"(r) : "f"(x), "f"(y)); return r;
}
__device__ __forceinline__ u64 pk1(float x) { return pk2(x, x); }
__device__ __forceinline__ float2 up2(u64 v) {
    float2 r; asm("mov.b64 {%0, %1}, %2;" : "=f"(r.x), "=f"(r.y) : "l"(v)); return r;
}
__device__ __forceinline__ u64 fma2(u64 a, u64 b, u64 c) {
    u64 d; asm("fma.rn.f32x2 %0, %1, %2, %3;" : "=l"(d) : "l"(a), "l"(b), "l"(c)); return d;
}

// ---------------- CSR build ----------------
__global__ void zero_cnt_kernel() {
    int i = blockIdx.x * blockDim.x + threadIdx.x;
    if (i < NN) g_cnt[i] = 0;
}

__global__ void hist_kernel(const int* __restrict__ h) {
    int e = blockIdx.x * blockDim.x + threadIdx.x;
    if (e < EE) atomicAdd(&g_cnt[h[e]], 1);
}

__global__ void reduce_cnt_kernel() {
    __shared__ int s[1024];
    int tid = threadIdx.x;
    int idx = blockIdx.x * 1024 + tid;
    s[tid] = (idx < NN) ? g_cnt[idx] : 0;
    __syncthreads();
    for (int o = 512; o > 0; o >>= 1) {
        if (tid < o) s[tid] += s[tid + o];
        __syncthreads();
    }
    if (tid == 0) g_bsum[blockIdx.x] = s[0];
}

__global__ void scan_bsums_kernel(int nblk) {
    __shared__ int s[160];
    int tid = threadIdx.x;
    if (tid < nblk) s[tid] = g_bsum[tid];
    __syncthreads();
    if (tid == 0) {
        int run = 0;
        for (int i = 0; i < nblk; i++) { int t = s[i]; s[i] = run; run += t; }
    }
    __syncthreads();
    if (tid < nblk) g_boff[tid] = s[tid];
}

__global__ void apply_scan_kernel() {
    __shared__ int s[1024];
    int tid = threadIdx.x;
    int idx = blockIdx.x * 1024 + tid;
    int v = (idx < NN) ? g_cnt[idx] : 0;
    s[tid] = v;
    __syncthreads();
    for (int off = 1; off < 1024; off <<= 1) {
        int t = (tid >= off) ? s[tid - off] : 0;
        __syncthreads();
        s[tid] += t;
        __syncthreads();
    }
    int excl = s[tid] - v + g_boff[blockIdx.x];
    if (idx < NN) { g_rowptr[idx] = excl; g_wp[idx] = excl; }
    if (blockIdx.x == 0 && tid == 0) g_rowptr[NN] = EE;
}

__global__ void scatter_kernel(const int* __restrict__ h, const int* __restrict__ t,
                               const float* __restrict__ adj) {
    int e = blockIdx.x * blockDim.x + threadIdx.x;
    if (e >= EE) return;
    int hn = h[e];
    int p  = atomicAdd(&g_wp[hn], 1);
    g_ecol[p] = t[e];
    g_eval[p] = adj[e];
}

// ---------------- init ----------------
__global__ void init_ek_kernel(const float4* __restrict__ ue, const float4* __restrict__ ie) {
    int i = blockIdx.x * blockDim.x + threadIdx.x;
    const int TOT = NN * DD / 4, UD4 = UN * DD / 4;
    if (i >= TOT) return;
    float4 v = (i < UD4) ? ue[i] : ie[i - UD4];
    ((float4*)g_ekA)[i]   = v;
    ((float4*)g_accum)[i] = v;
}

// ---------------- SpMM: gnn = A @ ek (16-lane group per node) + gnn norm ----------------
__global__ void __launch_bounds__(256) spmm_gnn_kernel(int layer, float* __restrict__ out) {
    const float* __restrict__ ekIn = layer ? g_ekB : g_ekA;
    int t0 = blockIdx.x * blockDim.x + threadIdx.x;
    int g = t0 >> 4;
    int l = threadIdx.x & 15;
    unsigned m = 0xFFFFu << (threadIdx.x & 16);
    int s = g_rowptr[g], e = g_rowptr[g + 1];
    float4 acc = make_float4(0.f, 0.f, 0.f, 0.f);
    for (int p = s; p < e; p++) {
        int   tt = __ldg(g_ecol + p);
        float v  = __ldg(g_eval + p);
        float4 x = *(const float4*)(ekIn + (size_t)tt * DD + l * 4);
        acc.x = fmaf(v, x.x, acc.x);
        acc.y = fmaf(v, x.y, acc.y);
        acc.z = fmaf(v, x.z, acc.z);
        acc.w = fmaf(v, x.w, acc.w);
    }
    *(float4*)(out + (size_t)g * DD + l * 4) = acc;
    float sg = acc.x * acc.x + acc.y * acc.y + acc.z * acc.z + acc.w * acc.w;
#pragma unroll
    for (int o = 8; o > 0; o >>= 1) sg += __shfl_xor_sync(m, sg, o);
    if (l == 0) g_inormg[g] = 1.f / fmaxf(sqrtf(sg), 1e-12f);
}

// ---------------- fused intent: softmax(ek@W)@W^T per 128-row tile + itl norm ----------------
#define TM   128
#define ASP  132
#define BTP  68
#define PSP  132
#define IT_SMEM_FLOATS (64 * ASP + 64 * KK + KK * BTP + TM * PSP)
#define IT_SMEM_BYTES  (IT_SMEM_FLOATS * 4)

__global__ void __launch_bounds__(256, 1)
intent_kernel(int layer, const float* __restrict__ W, float* __restrict__ outIntl,
              int nodeBase, int nodeCount) {
    const float* __restrict__ ekIn = layer ? g_ekB : g_ekA;
    extern __shared__ float sm[];
    float* As = sm;                  // [64][ASP]  A^T tile
    float* Bs = As + 64 * ASP;       // [64][128]  W
    float* Bt = Bs + 64 * KK;        // [128][BTP] W^T
    float* Ps = Bt + KK * BTP;       // [128][PSP] logits -> probs

    int tid = threadIdx.x;
    int tx = tid & 15, ty = tid >> 4;
    int rowTile = blockIdx.x * TM;

    // load W into Bs and Bt
#pragma unroll
    for (int it = 0; it < 8; it++) {
        int i = tid + it * 256;
        float4 v = ((const float4*)W)[i];
        int d = i >> 5;
        int k = (i << 2) & 127;
        *(float4*)(Bs + d * KK + k) = v;
        Bt[(k + 0) * BTP + d] = v.x;
        Bt[(k + 1) * BTP + d] = v.y;
        Bt[(k + 2) * BTP + d] = v.z;
        Bt[(k + 3) * BTP + d] = v.w;
    }
    // load A tile transposed (zero-pad OOB rows)
#pragma unroll
    for (int it = 0; it < 8; it++) {
        int i  = tid + it * 256;
        int rr = i >> 4;
        int d0 = (i << 2) & 63;
        float4 v = make_float4(0.f, 0.f, 0.f, 0.f);
        int r = rowTile + rr;
        if (r < nodeCount) v = *(const float4*)(ekIn + (size_t)(nodeBase + r) * DD + d0);
        As[(d0 + 0) * ASP + rr] = v.x;
        As[(d0 + 1) * ASP + rr] = v.y;
        As[(d0 + 2) * ASP + rr] = v.z;
        As[(d0 + 3) * ASP + rr] = v.w;
    }
    __syncthreads();

    const int r0 = ty * 8, k0 = tx * 8;

    // GEMM1 (packed f32x2): logits[128][128]
    u64 acc[8][4];
#pragma unroll
    for (int i = 0; i < 8; i++)
#pragma unroll
        for (int j = 0; j < 4; j++) acc[i][j] = 0ull;

#pragma unroll 4
    for (int d = 0; d < DD; d++) {
        float4 a0 = *(const float4*)(As + d * ASP + r0);
        float4 a1 = *(const float4*)(As + d * ASP + r0 + 4);
        float4 b0 = *(const float4*)(Bs + d * KK + k0);
        float4 b1 = *(const float4*)(Bs + d * KK + k0 + 4);
        u64 bp0 = pk2(b0.x, b0.y), bp1 = pk2(b0.z, b0.w);
        u64 bp2 = pk2(b1.x, b1.y), bp3 = pk2(b1.z, b1.w);
        float ar[8] = {a0.x, a0.y, a0.z, a0.w, a1.x, a1.y, a1.z, a1.w};
#pragma unroll
        for (int i = 0; i < 8; i++) {
            u64 ap = pk1(ar[i]);
            acc[i][0] = fma2(ap, bp0, acc[i][0]);
            acc[i][1] = fma2(ap, bp1, acc[i][1]);
            acc[i][2] = fma2(ap, bp2, acc[i][2]);
            acc[i][3] = fma2(ap, bp3, acc[i][3]);
        }
    }
#pragma unroll
    for (int i = 0; i < 8; i++) {
        u64* pr = (u64*)(Ps + (r0 + i) * PSP + k0);
        pr[0] = acc[i][0]; pr[1] = acc[i][1]; pr[2] = acc[i][2]; pr[3] = acc[i][3];
    }
    __syncthreads();

    // row softmax (warp per row)
    int warp = tid >> 5, lane = tid & 31;
    for (int rr = warp; rr < TM; rr += 8) {
        float4 v = *(float4*)(Ps + rr * PSP + lane * 4);
        float mx = fmaxf(fmaxf(v.x, v.y), fmaxf(v.z, v.w));
#pragma unroll
        for (int o = 16; o > 0; o >>= 1) mx = fmaxf(mx, __shfl_xor_sync(0xffffffffu, mx, o));
        float e0 = __expf(v.x - mx), e1 = __expf(v.y - mx);
        float e2 = __expf(v.z - mx), e3 = __expf(v.w - mx);
        float sum = e0 + e1 + e2 + e3;
#pragma unroll
        for (int o = 16; o > 0; o >>= 1) sum += __shfl_xor_sync(0xffffffffu, sum, o);
        float inv = 1.0f / sum;
        *(float4*)(Ps + rr * PSP + lane * 4) = make_float4(e0 * inv, e1 * inv, e2 * inv, e3 * inv);
    }
    __syncthreads();

    // GEMM2 (packed f32x2): out[128][64] = P @ W^T
    u64 acc2[8][2];
#pragma unroll
    for (int i = 0; i < 8; i++) { acc2[i][0] = 0ull; acc2[i][1] = 0ull; }
    const int d0o = tx * 4;
#pragma unroll 2
    for (int k = 0; k < KK; k += 4) {
        float4 p[8];
#pragma unroll
        for (int i = 0; i < 8; i++) p[i] = *(const float4*)(Ps + (r0 + i) * PSP + k);
        float4 c0 = *(const float4*)(Bt + (k + 0) * BTP + d0o);
        float4 c1 = *(const float4*)(Bt + (k + 1) * BTP + d0o);
        float4 c2 = *(const float4*)(Bt + (k + 2) * BTP + d0o);
        float4 c3 = *(const float4*)(Bt + (k + 3) * BTP + d0o);
        u64 b00 = pk2(c0.x, c0.y), b01 = pk2(c0.z, c0.w);
        u64 b10 = pk2(c1.x, c1.y), b11 = pk2(c1.z, c1.w);
        u64 b20 = pk2(c2.x, c2.y), b21 = pk2(c2.z, c2.w);
        u64 b30 = pk2(c3.x, c3.y), b31 = pk2(c3.z, c3.w);
#pragma unroll
        for (int i = 0; i < 8; i++) {
            u64 t;
            t = pk1(p[i].x); acc2[i][0] = fma2(t, b00, acc2[i][0]); acc2[i][1] = fma2(t, b01, acc2[i][1]);
            t = pk1(p[i].y); acc2[i][0] = fma2(t, b10, acc2[i][0]); acc2[i][1] = fma2(t, b11, acc2[i][1]);
            t = pk1(p[i].z); acc2[i][0] = fma2(t, b20, acc2[i][0]); acc2[i][1] = fma2(t, b21, acc2[i][1]);
            t = pk1(p[i].w); acc2[i][0] = fma2(t, b30, acc2[i][0]); acc2[i][1] = fma2(t, b31, acc2[i][1]);
        }
    }
    // epilogue: store + itl row norms (reduce over tx)
#pragma unroll
    for (int i = 0; i < 8; i++) {
        float2 lo = up2(acc2[i][0]);
        float2 hi = up2(acc2[i][1]);
        float4 o = make_float4(lo.x, lo.y, hi.x, hi.y);
        int r = rowTile + r0 + i;
        if (r < nodeCount)
            *(float4*)(outIntl + (size_t)(nodeBase + r) * DD + d0o) = o;
        float ns = o.x * o.x + o.y * o.y + o.z * o.z + o.w * o.w;
#pragma unroll
        for (int off = 8; off > 0; off >>= 1) ns += __shfl_xor_sync(0xffffffffu, ns, off);
        if (tx == 0 && r < nodeCount)
            g_inormi[nodeBase + r] = 1.f / fmaxf(sqrtf(ns), 1e-12f);
    }
}

// ---------------- fused alpha + spmm2 + combine (16-lane group per node) ----------------
__global__ void __launch_bounds__(256)
fused_alpha_kernel(int layer,
                   const float* __restrict__ gnn, const float* __restrict__ itl,
                   float* __restrict__ gaa, float* __restrict__ iaa,
                   float* __restrict__ finalOut) {
    const float* __restrict__ ekIn  = layer ? g_ekB : g_ekA;
    float*       __restrict__ ekOut = layer ? g_ekA : g_ekB;
    int t0 = blockIdx.x * blockDim.x + threadIdx.x;
    int g = t0 >> 4;
    int l = threadIdx.x & 15;
    unsigned m = 0xFFFFu << (threadIdx.x & 16);
    size_t ro = (size_t)g * DD + l * 4;

    float4 hg0 = *(const float4*)(gnn + ro);
    float4 hi0 = *(const float4*)(itl + ro);
    float ihg = g_inormg[g], ihi = g_inormi[g];
    float4 hg = make_float4(hg0.x * ihg, hg0.y * ihg, hg0.z * ihg, hg0.w * ihg);
    float4 hi = make_float4(hi0.x * ihi, hi0.y * ihi, hi0.z * ihi, hi0.w * ihi);

    float4 AG = make_float4(0.f, 0.f, 0.f, 0.f);
    float4 AI = make_float4(0.f, 0.f, 0.f, 0.f);
    float rsg = 0.f, rsi = 0.f;

    int s = g_rowptr[g], e = g_rowptr[g + 1];
    for (int p = s; p < e; p++) {
        int tt = __ldg(g_ecol + p);
        size_t to = (size_t)tt * DD + l * 4;
        float4 tg = *(const float4*)(gnn + to);
        float4 ti = *(const float4*)(itl + to);
        float4 tk = *(const float4*)(ekIn + to);
        float dg = hg.x * tg.x + hg.y * tg.y + hg.z * tg.z + hg.w * tg.w;
        float di = hi.x * ti.x + hi.y * ti.y + hi.z * ti.z + hi.w * ti.w;
#pragma unroll
        for (int o = 8; o > 0; o >>= 1) {
            dg += __shfl_xor_sync(m, dg, o);
            di += __shfl_xor_sync(m, di, o);
        }
        float ag = fmaf(dg, __ldg(g_inormg + tt), 1.f) * 0.5f;
        float ai = fmaf(di, __ldg(g_inormi + tt), 1.f) * 0.5f;
        AG.x = fmaf(ag, tk.x, AG.x); AG.y = fmaf(ag, tk.y, AG.y);
        AG.z = fmaf(ag, tk.z, AG.z); AG.w = fmaf(ag, tk.w, AG.w);
        AI.x = fmaf(ai, tk.x, AI.x); AI.y = fmaf(ai, tk.y, AI.y);
        AI.z = fmaf(ai, tk.z, AI.z); AI.w = fmaf(ai, tk.w, AI.w);
        rsg += ag;
        rsi += ai;
    }
    float dg_inv = rsg > 0.f ? 1.f / rsg : 0.f;
    float di_inv = rsi > 0.f ? 1.f / rsi : 0.f;
    float4 gv = make_float4(AG.x * dg_inv, AG.y * dg_inv, AG.z * dg_inv, AG.w * dg_inv);
    float4 iv = make_float4(AI.x * di_inv, AI.y * di_inv, AI.z * di_inv, AI.w * di_inv);
    *(float4*)(gaa + ro) = gv;
    *(float4*)(iaa + ro) = iv;

    // combine: e_{l+1} = gnn + intl + gaa + iaa + ek ; accum += e_{l+1}
    float4 ekv = *(const float4*)(ekIn + ro);
    float4 en;
    en.x = hg0.x + hi0.x + gv.x + iv.x + ekv.x;
    en.y = hg0.y + hi0.y + gv.y + iv.y + ekv.y;
    en.z = hg0.z + hi0.z + gv.z + iv.z + ekv.z;
    en.w = hg0.w + hi0.w + gv.w + iv.w + ekv.w;
    *(float4*)(ekOut + ro) = en;
    float4 ac = *(const float4*)(g_accum + ro);
    ac.x += en.x; ac.y += en.y; ac.z += en.z; ac.w += en.w;
    *(float4*)(g_accum + ro) = ac;
    if (finalOut) *(float4*)(finalOut + ro) = ac;
}

// ---------------- launch ----------------
extern "C" void kernel_launch(void* const* d_in, const int* in_sizes, int n_in,
                              void* d_out, int out_size) {
    const float* user_emb = (const float*)d_in[0];
    const float* item_emb = (const float*)d_in[1];
    const float* Wu       = (const float*)d_in[2];
    const float* Wi       = (const float*)d_in[3];
    const float* adj      = (const float*)d_in[4];
    const int*   h        = (const int*)d_in[5];
    const int*   t        = (const int*)d_in[6];
    (void)in_sizes; (void)n_in; (void)out_size;

    float* out = (float*)d_out;
    const size_t ND = (size_t)NN * DD;
    float* out_ua  = out;                    // [N*D] = ua | ia
    float* out_gnn = out + ND;               // [L][N][D]
    float* out_int = out_gnn + (size_t)LL * ND;
    float* out_gaa = out_int + (size_t)LL * ND;
    float* out_iaa = out_gaa + (size_t)LL * ND;

    cudaFuncSetAttribute(intent_kernel, cudaFuncAttributeMaxDynamicSharedMemorySize, IT_SMEM_BYTES);

    const int TPB = 256;
    const int SCAN_NB = (NN + 1023) / 1024;  // 147
    zero_cnt_kernel<<<(NN + TPB - 1) / TPB, TPB>>>();
    hist_kernel<<<(EE + TPB - 1) / TPB, TPB>>>(h);
    reduce_cnt_kernel<<<SCAN_NB, 1024>>>();
    scan_bsums_kernel<<<1, 256>>>(SCAN_NB);
    apply_scan_kernel<<<SCAN_NB, 1024>>>();
    scatter_kernel<<<(EE + TPB - 1) / TPB, TPB>>>(h, t, adj);
    init_ek_kernel<<<(NN * DD / 4 + TPB - 1) / TPB, TPB>>>((const float4*)user_emb,
                                                           (const float4*)item_emb);

    const int NODE_BLOCKS = (NN * 16 + TPB - 1) / TPB;   // 16-lane group per node
    for (int l = 0; l < LL; l++) {
        float* gnn = out_gnn + (size_t)l * ND;
        float* itl = out_int + (size_t)l * ND;
        float* gaa = out_gaa + (size_t)l * ND;
        float* iaa = out_iaa + (size_t)l * ND;

        spmm_gnn_kernel<<<NODE_BLOCKS, TPB>>>(l, gnn);
        intent_kernel<<<(UN + TM - 1) / TM, 256, IT_SMEM_BYTES>>>(l, Wu, itl, 0, UN);
        intent_kernel<<<(INC + TM - 1) / TM, 256, IT_SMEM_BYTES>>>(l, Wi, itl, UN, INC);
        fused_alpha_kernel<<<NODE_BLOCKS, TPB>>>(l, gnn, itl, gaa, iaa,
                                                 (l == LL - 1) ? out_ua : nullptr);
    }
}

// round 3
// speedup vs baseline: 1.5104x; 1.1509x over previous
#include <cuda_runtime.h>
#include <cuda_fp16.h>

// ---------------- problem constants ----------------
#define UN  100000
#define INC 50000
#define NN  150000
#define DD  64
#define KK  128
#define EE  1250000
#define LL  2

typedef unsigned long long u64;

// ---------------- device scratch (static; no allocations) ----------------
__device__ float g_ekA[NN * DD];
__device__ float g_ekB[NN * DD];
__device__ float g_accum[NN * DD];
__device__ int   g_cnt[NN];
__device__ int   g_rowptr[NN + 1];
__device__ int   g_wp[NN];
__device__ int   g_ecol[EE];
__device__ float g_eval[EE];
// packed normalized vectors: per node 16 chunks of 16B; chunk c = {gnn̂[4c..4c+3], itl̂[4c..4c+3]} as fp16
__device__ __half g_nrm[NN * 128];
__device__ int   g_bsum[160];
__device__ int   g_boff[160];

// ---------------- f32x2 packed-math helpers ----------------
__device__ __forceinline__ u64 pk2(float x, float y) {
    u64 r; asm("mov.b64 %0, {%1, %2};" : "=l"(r) : "f"(x), "f"(y)); return r;
}
__device__ __forceinline__ u64 pk1(float x) { return pk2(x, x); }
__device__ __forceinline__ float2 up2(u64 v) {
    float2 r; asm("mov.b64 {%0, %1}, %2;" : "=f"(r.x), "=f"(r.y) : "l"(v)); return r;
}
__device__ __forceinline__ u64 fma2(u64 a, u64 b, u64 c) {
    u64 d; asm("fma.rn.f32x2 %0, %1, %2, %3;" : "=l"(d) : "l"(a), "l"(b), "l"(c)); return d;
}

// ---------------- CSR build ----------------
__global__ void zero_cnt_kernel() {
    int i = blockIdx.x * blockDim.x + threadIdx.x;
    if (i < NN) g_cnt[i] = 0;
}

__global__ void hist_kernel(const int* __restrict__ h) {
    int e = blockIdx.x * blockDim.x + threadIdx.x;
    if (e < EE) atomicAdd(&g_cnt[h[e]], 1);
}

__global__ void reduce_cnt_kernel() {
    __shared__ int s[1024];
    int tid = threadIdx.x;
    int idx = blockIdx.x * 1024 + tid;
    s[tid] = (idx < NN) ? g_cnt[idx] : 0;
    __syncthreads();
    for (int o = 512; o > 0; o >>= 1) {
        if (tid < o) s[tid] += s[tid + o];
        __syncthreads();
    }
    if (tid == 0) g_bsum[blockIdx.x] = s[0];
}

__global__ void scan_bsums_kernel(int nblk) {
    __shared__ int s[160];
    int tid = threadIdx.x;
    if (tid < nblk) s[tid] = g_bsum[tid];
    __syncthreads();
    if (tid == 0) {
        int run = 0;
        for (int i = 0; i < nblk; i++) { int t = s[i]; s[i] = run; run += t; }
    }
    __syncthreads();
    if (tid < nblk) g_boff[tid] = s[tid];
}

__global__ void apply_scan_kernel() {
    __shared__ int s[1024];
    int tid = threadIdx.x;
    int idx = blockIdx.x * 1024 + tid;
    int v = (idx < NN) ? g_cnt[idx] : 0;
    s[tid] = v;
    __syncthreads();
    for (int off = 1; off < 1024; off <<= 1) {
        int t = (tid >= off) ? s[tid - off] : 0;
        __syncthreads();
        s[tid] += t;
        __syncthreads();
    }
    int excl = s[tid] - v + g_boff[blockIdx.x];
    if (idx < NN) { g_rowptr[idx] = excl; g_wp[idx] = excl; }
    if (blockIdx.x == 0 && tid == 0) g_rowptr[NN] = EE;
}

__global__ void scatter_kernel(const int* __restrict__ h, const int* __restrict__ t,
                               const float* __restrict__ adj) {
    int e = blockIdx.x * blockDim.x + threadIdx.x;
    if (e >= EE) return;
    int hn = h[e];
    int p  = atomicAdd(&g_wp[hn], 1);
    g_ecol[p] = t[e];
    g_eval[p] = adj[e];
}

// ---------------- init ----------------
__global__ void init_ek_kernel(const float4* __restrict__ ue, const float4* __restrict__ ie) {
    int i = blockIdx.x * blockDim.x + threadIdx.x;
    const int TOT = NN * DD / 4, UD4 = UN * DD / 4;
    if (i >= TOT) return;
    float4 v = (i < UD4) ? ue[i] : ie[i - UD4];
    ((float4*)g_ekA)[i]   = v;
    ((float4*)g_accum)[i] = v;
}

// ---------------- SpMM: gnn = A @ ek (16-lane group per node); writes gnn + fp16 gnn̂ ----------------
__global__ void __launch_bounds__(256) spmm_gnn_kernel(int layer, float* __restrict__ out) {
    const float* __restrict__ ekIn = layer ? g_ekB : g_ekA;
    int t0 = blockIdx.x * blockDim.x + threadIdx.x;
    int g = t0 >> 4;
    int l = threadIdx.x & 15;
    unsigned m = 0xFFFFu << (threadIdx.x & 16);
    int s = g_rowptr[g], e = g_rowptr[g + 1];
    float4 acc = make_float4(0.f, 0.f, 0.f, 0.f);

    int p = s;
    int   tt = 0; float v = 0.f; float4 x = make_float4(0.f, 0.f, 0.f, 0.f);
    if (p < e) {
        tt = __ldg(g_ecol + p);
        v  = __ldg(g_eval + p);
        x  = *(const float4*)(ekIn + (size_t)tt * DD + l * 4);
    }
    while (p < e) {
        float  cv = v;
        float4 cx = x;
        p++;
        if (p < e) {
            tt = __ldg(g_ecol + p);
            v  = __ldg(g_eval + p);
            x  = *(const float4*)(ekIn + (size_t)tt * DD + l * 4);
        }
        acc.x = fmaf(cv, cx.x, acc.x);
        acc.y = fmaf(cv, cx.y, acc.y);
        acc.z = fmaf(cv, cx.z, acc.z);
        acc.w = fmaf(cv, cx.w, acc.w);
    }
    *(float4*)(out + (size_t)g * DD + l * 4) = acc;
    float sg = acc.x * acc.x + acc.y * acc.y + acc.z * acc.z + acc.w * acc.w;
#pragma unroll
    for (int o = 8; o > 0; o >>= 1) sg += __shfl_xor_sync(m, sg, o);
    float inv = 1.f / fmaxf(sqrtf(sg), 1e-12f);
    __half2 h0 = __floats2half2_rn(acc.x * inv, acc.y * inv);
    __half2 h1 = __floats2half2_rn(acc.z * inv, acc.w * inv);
    uint2 u;
    u.x = *(unsigned*)&h0;
    u.y = *(unsigned*)&h1;
    ((uint2*)g_nrm)[(size_t)g * 32 + l * 2] = u;   // g-part of chunk l
}

// ---------------- fused intent: softmax(ek@W)@W^T per 128-row tile; writes itl + fp16 itl̂ ----------------
#define TM   128
#define ASP  132
#define BTP  68
#define PSP  132
#define IT_SMEM_FLOATS (64 * ASP + 64 * KK + KK * BTP + TM * PSP)
#define IT_SMEM_BYTES  (IT_SMEM_FLOATS * 4)

__global__ void __launch_bounds__(256, 1)
intent_kernel(int layer, const float* __restrict__ W, float* __restrict__ outIntl,
              int nodeBase, int nodeCount) {
    const float* __restrict__ ekIn = layer ? g_ekB : g_ekA;
    extern __shared__ float sm[];
    float* As = sm;                  // [64][ASP]  A^T tile
    float* Bs = As + 64 * ASP;       // [64][128]  W
    float* Bt = Bs + 64 * KK;        // [128][BTP] W^T
    float* Ps = Bt + KK * BTP;       // [128][PSP] logits -> probs

    int tid = threadIdx.x;
    int tx = tid & 15, ty = tid >> 4;
    int rowTile = blockIdx.x * TM;

#pragma unroll
    for (int it = 0; it < 8; it++) {
        int i = tid + it * 256;
        float4 v = ((const float4*)W)[i];
        int d = i >> 5;
        int k = (i << 2) & 127;
        *(float4*)(Bs + d * KK + k) = v;
        Bt[(k + 0) * BTP + d] = v.x;
        Bt[(k + 1) * BTP + d] = v.y;
        Bt[(k + 2) * BTP + d] = v.z;
        Bt[(k + 3) * BTP + d] = v.w;
    }
#pragma unroll
    for (int it = 0; it < 8; it++) {
        int i  = tid + it * 256;
        int rr = i >> 4;
        int d0 = (i << 2) & 63;
        float4 v = make_float4(0.f, 0.f, 0.f, 0.f);
        int r = rowTile + rr;
        if (r < nodeCount) v = *(const float4*)(ekIn + (size_t)(nodeBase + r) * DD + d0);
        As[(d0 + 0) * ASP + rr] = v.x;
        As[(d0 + 1) * ASP + rr] = v.y;
        As[(d0 + 2) * ASP + rr] = v.z;
        As[(d0 + 3) * ASP + rr] = v.w;
    }
    __syncthreads();

    const int r0 = ty * 8, k0 = tx * 8;

    // GEMM1 (packed f32x2)
    u64 acc[8][4];
#pragma unroll
    for (int i = 0; i < 8; i++)
#pragma unroll
        for (int j = 0; j < 4; j++) acc[i][j] = 0ull;

#pragma unroll 4
    for (int d = 0; d < DD; d++) {
        float4 a0 = *(const float4*)(As + d * ASP + r0);
        float4 a1 = *(const float4*)(As + d * ASP + r0 + 4);
        float4 b0 = *(const float4*)(Bs + d * KK + k0);
        float4 b1 = *(const float4*)(Bs + d * KK + k0 + 4);
        u64 bp0 = pk2(b0.x, b0.y), bp1 = pk2(b0.z, b0.w);
        u64 bp2 = pk2(b1.x, b1.y), bp3 = pk2(b1.z, b1.w);
        float ar[8] = {a0.x, a0.y, a0.z, a0.w, a1.x, a1.y, a1.z, a1.w};
#pragma unroll
        for (int i = 0; i < 8; i++) {
            u64 ap = pk1(ar[i]);
            acc[i][0] = fma2(ap, bp0, acc[i][0]);
            acc[i][1] = fma2(ap, bp1, acc[i][1]);
            acc[i][2] = fma2(ap, bp2, acc[i][2]);
            acc[i][3] = fma2(ap, bp3, acc[i][3]);
        }
    }
#pragma unroll
    for (int i = 0; i < 8; i++) {
        u64* pr = (u64*)(Ps + (r0 + i) * PSP + k0);
        pr[0] = acc[i][0]; pr[1] = acc[i][1]; pr[2] = acc[i][2]; pr[3] = acc[i][3];
    }
    __syncthreads();

    // row softmax
    int warp = tid >> 5, lane = tid & 31;
    for (int rr = warp; rr < TM; rr += 8) {
        float4 v = *(float4*)(Ps + rr * PSP + lane * 4);
        float mx = fmaxf(fmaxf(v.x, v.y), fmaxf(v.z, v.w));
#pragma unroll
        for (int o = 16; o > 0; o >>= 1) mx = fmaxf(mx, __shfl_xor_sync(0xffffffffu, mx, o));
        float e0 = __expf(v.x - mx), e1 = __expf(v.y - mx);
        float e2 = __expf(v.z - mx), e3 = __expf(v.w - mx);
        float sum = e0 + e1 + e2 + e3;
#pragma unroll
        for (int o = 16; o > 0; o >>= 1) sum += __shfl_xor_sync(0xffffffffu, sum, o);
        float inv = 1.0f / sum;
        *(float4*)(Ps + rr * PSP + lane * 4) = make_float4(e0 * inv, e1 * inv, e2 * inv, e3 * inv);
    }
    __syncthreads();

    // GEMM2 (packed f32x2)
    u64 acc2[8][2];
#pragma unroll
    for (int i = 0; i < 8; i++) { acc2[i][0] = 0ull; acc2[i][1] = 0ull; }
    const int d0o = tx * 4;
#pragma unroll 2
    for (int k = 0; k < KK; k += 4) {
        float4 p[8];
#pragma unroll
        for (int i = 0; i < 8; i++) p[i] = *(const float4*)(Ps + (r0 + i) * PSP + k);
        float4 c0 = *(const float4*)(Bt + (k + 0) * BTP + d0o);
        float4 c1 = *(const float4*)(Bt + (k + 1) * BTP + d0o);
        float4 c2 = *(const float4*)(Bt + (k + 2) * BTP + d0o);
        float4 c3 = *(const float4*)(Bt + (k + 3) * BTP + d0o);
        u64 b00 = pk2(c0.x, c0.y), b01 = pk2(c0.z, c0.w);
        u64 b10 = pk2(c1.x, c1.y), b11 = pk2(c1.z, c1.w);
        u64 b20 = pk2(c2.x, c2.y), b21 = pk2(c2.z, c2.w);
        u64 b30 = pk2(c3.x, c3.y), b31 = pk2(c3.z, c3.w);
#pragma unroll
        for (int i = 0; i < 8; i++) {
            u64 t;
            t = pk1(p[i].x); acc2[i][0] = fma2(t, b00, acc2[i][0]); acc2[i][1] = fma2(t, b01, acc2[i][1]);
            t = pk1(p[i].y); acc2[i][0] = fma2(t, b10, acc2[i][0]); acc2[i][1] = fma2(t, b11, acc2[i][1]);
            t = pk1(p[i].z); acc2[i][0] = fma2(t, b20, acc2[i][0]); acc2[i][1] = fma2(t, b21, acc2[i][1]);
            t = pk1(p[i].w); acc2[i][0] = fma2(t, b30, acc2[i][0]); acc2[i][1] = fma2(t, b31, acc2[i][1]);
        }
    }
    // epilogue: store + itl̂ fp16 write
#pragma unroll
    for (int i = 0; i < 8; i++) {
        float2 lo = up2(acc2[i][0]);
        float2 hi = up2(acc2[i][1]);
        float4 o = make_float4(lo.x, lo.y, hi.x, hi.y);
        int r = rowTile + r0 + i;
        bool ok = (r < nodeCount);
        if (ok) *(float4*)(outIntl + (size_t)(nodeBase + r) * DD + d0o) = o;
        float ns = o.x * o.x + o.y * o.y + o.z * o.z + o.w * o.w;
#pragma unroll
        for (int off = 8; off > 0; off >>= 1) ns += __shfl_xor_sync(0xffffffffu, ns, off);
        float inv = 1.f / fmaxf(sqrtf(ns), 1e-12f);
        if (ok) {
            __half2 h0 = __floats2half2_rn(o.x * inv, o.y * inv);
            __half2 h1 = __floats2half2_rn(o.z * inv, o.w * inv);
            uint2 u;
            u.x = *(unsigned*)&h0;
            u.y = *(unsigned*)&h1;
            ((uint2*)g_nrm)[(size_t)(nodeBase + r) * 32 + tx * 2 + 1];   // address compute only
            ((uint2*)g_nrm)[(size_t)(nodeBase + r) * 32 + tx * 2 + 1] = u;  // i-part of chunk tx
        }
    }
}

// ---------------- fused alpha + spmm2 + combine (16-lane group per node) ----------------
__global__ void __launch_bounds__(256)
fused_alpha_kernel(int layer,
                   const float* __restrict__ gnn, const float* __restrict__ itl,
                   float* __restrict__ gaa, float* __restrict__ iaa,
                   float* __restrict__ finalOut) {
    const float* __restrict__ ekIn  = layer ? g_ekB : g_ekA;
    float*       __restrict__ ekOut = layer ? g_ekA : g_ekB;
    int t0 = blockIdx.x * blockDim.x + threadIdx.x;
    int g = t0 >> 4;
    int l = threadIdx.x & 15;
    unsigned m = 0xFFFFu << (threadIdx.x & 16);
    size_t ro = (size_t)g * DD + l * 4;
    const uint4* __restrict__ nrm4 = (const uint4*)g_nrm;

    // head normalized chunk (fp16 -> fp32 once)
    uint4 hn = nrm4[(size_t)g * 16 + l];
    float2 hg01 = __half22float2(*(__half2*)&hn.x);
    float2 hg23 = __half22float2(*(__half2*)&hn.y);
    float2 hi01 = __half22float2(*(__half2*)&hn.z);
    float2 hi23 = __half22float2(*(__half2*)&hn.w);

    float4 AG = make_float4(0.f, 0.f, 0.f, 0.f);
    float4 AI = make_float4(0.f, 0.f, 0.f, 0.f);
    float rsg = 0.f, rsi = 0.f;

    int s = g_rowptr[g], e = g_rowptr[g + 1];
    int p = s;
    uint4 tn = make_uint4(0, 0, 0, 0);
    float4 tk = make_float4(0.f, 0.f, 0.f, 0.f);
    if (p < e) {
        int tt = __ldg(g_ecol + p);
        tn = nrm4[(size_t)tt * 16 + l];
        tk = *(const float4*)(ekIn + (size_t)tt * DD + l * 4);
    }
    while (p < e) {
        uint4  cn = tn;
        float4 ck = tk;
        p++;
        if (p < e) {
            int tt = __ldg(g_ecol + p);
            tn = nrm4[(size_t)tt * 16 + l];
            tk = *(const float4*)(ekIn + (size_t)tt * DD + l * 4);
        }
        float2 tg01 = __half22float2(*(__half2*)&cn.x);
        float2 tg23 = __half22float2(*(__half2*)&cn.y);
        float2 ti01 = __half22float2(*(__half2*)&cn.z);
        float2 ti23 = __half22float2(*(__half2*)&cn.w);
        float dg = hg01.x * tg01.x + hg01.y * tg01.y + hg23.x * tg23.x + hg23.y * tg23.y;
        float di = hi01.x * ti01.x + hi01.y * ti01.y + hi23.x * ti23.x + hi23.y * ti23.y;
#pragma unroll
        for (int o = 8; o > 0; o >>= 1) {
            dg += __shfl_xor_sync(m, dg, o);
            di += __shfl_xor_sync(m, di, o);
        }
        float ag = (dg + 1.f) * 0.5f;
        float ai = (di + 1.f) * 0.5f;
        AG.x = fmaf(ag, ck.x, AG.x); AG.y = fmaf(ag, ck.y, AG.y);
        AG.z = fmaf(ag, ck.z, AG.z); AG.w = fmaf(ag, ck.w, AG.w);
        AI.x = fmaf(ai, ck.x, AI.x); AI.y = fmaf(ai, ck.y, AI.y);
        AI.z = fmaf(ai, ck.z, AI.z); AI.w = fmaf(ai, ck.w, AI.w);
        rsg += ag;
        rsi += ai;
    }
    float dg_inv = rsg > 0.f ? 1.f / rsg : 0.f;
    float di_inv = rsi > 0.f ? 1.f / rsi : 0.f;
    float4 gv = make_float4(AG.x * dg_inv, AG.y * dg_inv, AG.z * dg_inv, AG.w * dg_inv);
    float4 iv = make_float4(AI.x * di_inv, AI.y * di_inv, AI.z * di_inv, AI.w * di_inv);
    *(float4*)(gaa + ro) = gv;
    *(float4*)(iaa + ro) = iv;

    // combine: e_{l+1} = gnn + intl + gaa + iaa + ek ; accum += e_{l+1}
    float4 hg0 = *(const float4*)(gnn + ro);
    float4 hi0 = *(const float4*)(itl + ro);
    float4 ekv = *(const float4*)(ekIn + ro);
    float4 en;
    en.x = hg0.x + hi0.x + gv.x + iv.x + ekv.x;
    en.y = hg0.y + hi0.y + gv.y + iv.y + ekv.y;
    en.z = hg0.z + hi0.z + gv.z + iv.z + ekv.z;
    en.w = hg0.w + hi0.w + gv.w + iv.w + ekv.w;
    float4 ac = *(const float4*)(g_accum + ro);
    ac.x += en.x; ac.y += en.y; ac.z += en.z; ac.w += en.w;
    if (finalOut) {
        *(float4*)(finalOut + ro) = ac;      // last layer: ekOut/accum never read again
    } else {
        *(float4*)(ekOut + ro) = en;
        *(float4*)(g_accum + ro) = ac;
    }
}

// ---------------- launch ----------------
extern "C" void kernel_launch(void* const* d_in, const int* in_sizes, int n_in,
                              void* d_out, int out_size) {
    const float* user_emb = (const float*)d_in[0];
    const float* item_emb = (const float*)d_in[1];
    const float* Wu       = (const float*)d_in[2];
    const float* Wi       = (const float*)d_in[3];
    const float* adj      = (const float*)d_in[4];
    const int*   h        = (const int*)d_in[5];
    const int*   t        = (const int*)d_in[6];
    (void)in_sizes; (void)n_in; (void)out_size;

    float* out = (float*)d_out;
    const size_t ND = (size_t)NN * DD;
    float* out_ua  = out;                    // [N*D] = ua | ia
    float* out_gnn = out + ND;               // [L][N][D]
    float* out_int = out_gnn + (size_t)LL * ND;
    float* out_gaa = out_int + (size_t)LL * ND;
    float* out_iaa = out_gaa + (size_t)LL * ND;

    cudaFuncSetAttribute(intent_kernel, cudaFuncAttributeMaxDynamicSharedMemorySize, IT_SMEM_BYTES);

    const int TPB = 256;
    const int SCAN_NB = (NN + 1023) / 1024;  // 147
    zero_cnt_kernel<<<(NN + TPB - 1) / TPB, TPB>>>();
    hist_kernel<<<(EE + TPB - 1) / TPB, TPB>>>(h);
    reduce_cnt_kernel<<<SCAN_NB, 1024>>>();
    scan_bsums_kernel<<<1, 256>>>(SCAN_NB);
    apply_scan_kernel<<<SCAN_NB, 1024>>>();
    scatter_kernel<<<(EE + TPB - 1) / TPB, TPB>>>(h, t, adj);
    init_ek_kernel<<<(NN * DD / 4 + TPB - 1) / TPB, TPB>>>((const float4*)user_emb,
                                                           (const float4*)item_emb);

    const int NODE_BLOCKS = (NN * 16 + TPB - 1) / TPB;   // 16-lane group per node
    for (int l = 0; l < LL; l++) {
        float* gnn = out_gnn + (size_t)l * ND;
        float* itl = out_int + (size_t)l * ND;
        float* gaa = out_gaa + (size_t)l * ND;
        float* iaa = out_iaa + (size_t)l * ND;

        spmm_gnn_kernel<<<NODE_BLOCKS, TPB>>>(l, gnn);
        intent_kernel<<<(UN + TM - 1) / TM, 256, IT_SMEM_BYTES>>>(l, Wu, itl, 0, UN);
        intent_kernel<<<(INC + TM - 1) / TM, 256, IT_SMEM_BYTES>>>(l, Wi, itl, UN, INC);
        fused_alpha_kernel<<<NODE_BLOCKS, TPB>>>(l, gnn, itl, gaa, iaa,
                                                 (l == LL - 1) ? out_ua : nullptr);
    }
}